// round 14
// baseline (speedup 1.0000x reference)
#include <cuda_runtime.h>
#include <cuda_fp16.h>
#include <mma.h>
#include <math.h>

using namespace nvcuda;

#define NNODES 20000
#define NEDGES 200000
#define NC     32
#define FDIM   13
#define FHID   64
#define NREP   10
#define OUTC   (NC * (NREP + 1))   // 352
#define MPAD   20032               // NNODES padded to 64

// Scratch (__device__ globals; allocation-free rule). Zero-initialized at load.
__device__ __half g_Q[(size_t)MPAD * 2048];            // 82 MB, layout [n][k*32+o]
__device__ __half g_h1[(size_t)NEDGES * FHID];         // 25.6 MB (edge order)
__device__ __half g_h1s[(size_t)(NEDGES + 16) * FHID]; // src-sorted (+16 pad rows)
__device__ __half g_fW2pp[32 * 2048];                  // permuted fW2: [i][k*32+o]
__device__ __half g_hxh[(size_t)MPAD * NC];            // fp16 hx (initial only)
__device__ __half g_msgh[(size_t)NEDGES * NC];         // msgs fp16, SRC-sorted
__device__ float  g_deg[NNODES];
__device__ int    g_cnt[NNODES], g_cur[NNODES];        // src CSR build
__device__ int    g_cntd[NNODES], g_curd[NNODES];      // dst CSR build
__device__ int    g_off[NNODES + 1];                   // src CSR offsets
__device__ int    g_offd[NNODES + 1];                  // dst CSR offsets
__device__ int    g_spos[NEDGES];                      // dst-sorted pos -> src-sorted pos

// ---------------------------------------------------------------------------
// launch 1 — prep0: h1 (warp/edge) + degree counts + copy0 + fW2 permute
// ---------------------------------------------------------------------------
__global__ void prep0_kernel(const float* __restrict__ ef,
                             const float* __restrict__ fW1,
                             const float* __restrict__ fb1,
                             const float* __restrict__ fW2,
                             const float* __restrict__ hx,
                             const int* __restrict__ src,
                             const int* __restrict__ dst,
                             float* __restrict__ out,
                             int N, int E) {
    int gtid = blockIdx.x * blockDim.x + threadIdx.x;
    int e    = gtid >> 5;
    int lane = gtid & 31;

    if (e < E) {
        float efv = (lane < FDIM) ? ef[(size_t)e * FDIM + lane] : 0.f;
        float a0 = fb1[lane], a1 = fb1[lane + 32];
#pragma unroll
        for (int j = 0; j < FDIM; j++) {
            float x = __shfl_sync(0xffffffffu, efv, j);
            a0 = fmaf(x, fW1[j * FHID + lane],      a0);
            a1 = fmaf(x, fW1[j * FHID + lane + 32], a1);
        }
        g_h1[(size_t)e * FHID + lane]      = __float2half_rn(fmaxf(a0, 0.f));
        g_h1[(size_t)e * FHID + lane + 32] = __float2half_rn(fmaxf(a1, 0.f));
    }
    if (gtid < E) {
        atomicAdd(&g_cnt[src[gtid]], 1);
        atomicAdd(&g_cntd[dst[gtid]], 1);
    }
    if (gtid < N * NC) {
        float v = hx[gtid];
        out[(size_t)(gtid >> 5) * OUTC + (gtid & 31)] = v;
        g_hxh[gtid] = __float2half_rn(v);
    }
    if (gtid < (MPAD - NNODES) * NC)
        g_hxh[(size_t)NNODES * NC + gtid] = __float2half_rn(0.f);
    // fW2 permute: g_fW2pp[i*2048 + k*32 + o] = fW2[k*1024 + i*32 + o]
    if (gtid < 32 * 2048) {
        int i = gtid >> 11, rem = gtid & 2047, k = rem >> 5, o = rem & 31;
        g_fW2pp[gtid] = __float2half_rn(fW2[k * 1024 + i * 32 + o]);
    }
}

// ---------------------------------------------------------------------------
// launch 2 — qgemm0 (initial Q from hx) + CSR scans in block (0,0)
// ---------------------------------------------------------------------------
#define QBS_LD 136
#define MT_PER_BLK 8

__global__ void qgemm_kernel(int N) {
    __shared__ __align__(16) __half Bs[32 * QBS_LD];
    __shared__ int part[256];

    const int tid = threadIdx.x;
    const int wid = tid >> 5;
    const int wm = wid & 3, wn = wid >> 2;
    const int n0 = blockIdx.y * 128;

    if (blockIdx.x == 0 && blockIdx.y == 0) {       // scans (needs prep0 counts)
        int chunk = (N + 255) / 256;
        int lo = tid * chunk, hi = min(lo + chunk, N);
        int s = 0;
        for (int i = lo; i < hi; i++) s += g_cnt[i];
        part[tid] = s;
        __syncthreads();
        if (tid == 0) {
            int run = 0;
            for (int i = 0; i < 256; i++) { int v = part[i]; part[i] = run; run += v; }
            g_off[N] = run;
        }
        __syncthreads();
        int run = part[tid];
        for (int i = lo; i < hi; i++) { g_off[i] = run; run += g_cnt[i]; }
        __syncthreads();

        s = 0;
        for (int i = lo; i < hi; i++) s += g_cntd[i];
        part[tid] = s;
        __syncthreads();
        if (tid == 0) {
            int run2 = 0;
            for (int i = 0; i < 256; i++) { int v = part[i]; part[i] = run2; run2 += v; }
            g_offd[N] = run2;
        }
        __syncthreads();
        run = part[tid];
        for (int i = lo; i < hi; i++) { g_offd[i] = run; run += g_cntd[i]; }
        __syncthreads();
    }

#pragma unroll
    for (int i = tid; i < 512; i += 256) {
        int r = i >> 4, s = i & 15;
        *(int4*)(Bs + r * QBS_LD + s * 8) =
            *(const int4*)(g_fW2pp + (size_t)r * 2048 + n0 + s * 8);
    }
    __syncthreads();

    wmma::fragment<wmma::matrix_b, 16, 16, 16, __half, wmma::row_major> bf[2][4];
#pragma unroll
    for (int k = 0; k < 2; k++)
#pragma unroll
        for (int j = 0; j < 4; j++)
            wmma::load_matrix_sync(bf[k][j], Bs + (k * 16) * QBS_LD + wn * 64 + j * 16, QBS_LD);

    for (int mi = 0; mi < MT_PER_BLK; mi++) {
        int m0 = (blockIdx.x * MT_PER_BLK + mi) * 64;
        if (m0 >= MPAD) break;

        wmma::fragment<wmma::accumulator, 16, 16, 16, float> acc[4];
#pragma unroll
        for (int j = 0; j < 4; j++) wmma::fill_fragment(acc[j], 0.0f);
#pragma unroll
        for (int k = 0; k < 2; k++) {
            wmma::fragment<wmma::matrix_a, 16, 16, 16, __half, wmma::row_major> af;
            wmma::load_matrix_sync(af, g_hxh + (size_t)(m0 + wm * 16) * NC + k * 16, NC);
#pragma unroll
            for (int j = 0; j < 4; j++)
                wmma::mma_sync(acc[j], af, bf[k][j], acc[j]);
        }
#pragma unroll
        for (int j = 0; j < 4; j++) {
            wmma::fragment<wmma::accumulator, 16, 16, 16, __half> hc;
#pragma unroll
            for (int i = 0; i < hc.num_elements; i++)
                hc.x[i] = __float2half_rn(acc[j].x[i]);
            wmma::store_matrix_sync(g_Q + (size_t)(m0 + wm * 16) * 2048 + n0 + wn * 64 + j * 16,
                                    hc, 2048, wmma::mem_row_major);
        }
    }
}

// launch 3 — scatter: warp per edge. h1 -> src-sorted g_h1s; spos inverse map.
__global__ void scatter_kernel(const int* __restrict__ src,
                               const int* __restrict__ dst, int N, int E) {
    int gtid = blockIdx.x * blockDim.x + threadIdx.x;
    int e    = gtid >> 5;
    int lane = gtid & 31;
    if (e < E) {
        int ps = 0;
        if (lane == 0) {
            int s = src[e], d = dst[e];
            ps = g_off[s]  + atomicAdd(&g_cur[s], 1);
            int pd = g_offd[d] + atomicAdd(&g_curd[d], 1);
            g_spos[pd] = ps;
        }
        ps = __shfl_sync(0xffffffffu, ps, 0);
        ((int*)g_h1s)[(size_t)ps * 32 + lane] = ((const int*)g_h1)[(size_t)e * 32 + lane];
    }
    if (gtid < N) g_deg[gtid] = 1.0f / fmaxf((float)g_cntd[gtid], 1.0f);
}

// ---------------------------------------------------------------------------
// launch 4 (PROFILED) — msg: warp per node, tensor cores, smem-staged Q row.
// MSG[d x 32] = H1s[d x 64] @ Q[n] (64 x 32 k-major), fp32 accum, fp16 out.
// ---------------------------------------------------------------------------
#define QW_LD 40
__global__ void msg_kernel(const float* __restrict__ out,
                           const float* __restrict__ fb2,
                           int N, int t) {
    __shared__ __align__(16) __half Qw[8][64 * QW_LD];   // 5,120 B per warp
    int n    = (blockIdx.x * blockDim.x + threadIdx.x) >> 5;
    int lane = threadIdx.x & 31;
    int w    = (threadIdx.x >> 5) & 7;
    if (n >= N) return;
    int start = __ldg(&g_off[n]);
    int d = __ldg(&g_off[n + 1]) - start;
    if (d == 0) return;

    // stage Q row (4KB): lane copies rows lane and lane+32 (64B each, coalesced)
    {
        const int4* qsrc = (const int4*)(g_Q + (size_t)n * 2048);
#pragma unroll
        for (int rr = 0; rr < 2; rr++) {
            int r = lane + rr * 32;
            int4* dstp = (int4*)(&Qw[w][r * QW_LD]);
#pragma unroll
            for (int j = 0; j < 4; j++)
                dstp[j] = __ldg(qsrc + r * 4 + j);
        }
    }

    // bias: bn[o] = sum_i hx[n,i] * fb2[i*32+o]
    float hxl = out[(size_t)n * OUTC + (size_t)(t - 1) * NC + lane];
    float bn = 0.f;
#pragma unroll
    for (int i = 0; i < NC; i++)
        bn = fmaf(__shfl_sync(0xffffffffu, hxl, i), fb2[i * 32 + lane], bn);
    __syncwarp();

    wmma::fragment<wmma::matrix_b, 16, 16, 16, __half, wmma::row_major> bf[4][2];
#pragma unroll
    for (int kk = 0; kk < 4; kk++)
#pragma unroll
        for (int j = 0; j < 2; j++)
            wmma::load_matrix_sync(bf[kk][j], &Qw[w][(kk * 16) * QW_LD + j * 16], QW_LD);
    __syncwarp();

    float* Cst = (float*)(&Qw[w][0]);   // alias warp staging (B-frags in regs)
    for (int mt = 0; mt < d; mt += 16) {
        wmma::fragment<wmma::accumulator, 16, 16, 16, float> acc0, acc1;
        wmma::fill_fragment(acc0, 0.0f);
        wmma::fill_fragment(acc1, 0.0f);
#pragma unroll
        for (int kk = 0; kk < 4; kk++) {
            wmma::fragment<wmma::matrix_a, 16, 16, 16, __half, wmma::row_major> af;
            wmma::load_matrix_sync(af, g_h1s + (size_t)(start + mt) * FHID + kk * 16, FHID);
            wmma::mma_sync(acc0, af, bf[kk][0], acc0);
            wmma::mma_sync(acc1, af, bf[kk][1], acc1);
        }
        wmma::store_matrix_sync(Cst,      acc0, 32, wmma::mem_row_major);
        wmma::store_matrix_sync(Cst + 16, acc1, 32, wmma::mem_row_major);
        __syncwarp();
        int rows = min(16, d - mt);
        for (int r = 0; r < rows; r++)
            g_msgh[(size_t)(start + mt + r) * NC + lane] =
                __float2half_rn(Cst[r * 32 + lane] + bn);
        __syncwarp();
    }
}

// ---------------------------------------------------------------------------
// gruq: FUSED GRU + next-iteration Q. Block = 16 nodes, 8 warps.
// Phase 1: warp w does GRU for nodes n0+w, n0+w+8 -> out + smem As (fp16).
// Phase 2 (unless last iter): Q[16 x 2048] tile = As @ fW2pp via wmma.
// ---------------------------------------------------------------------------
__global__ void gruq_kernel(float* __restrict__ out,
                            const float* __restrict__ Wi,
                            const float* __restrict__ Wh,
                            const float* __restrict__ bi,
                            const float* __restrict__ bh,
                            int N, int t, int last) {
    __shared__ __align__(16) __half As[16 * 40];
    const int n0   = blockIdx.x * 16;
    const int tid  = threadIdx.x;
    const int w    = tid >> 5;
    const int lane = tid & 31;

#pragma unroll
    for (int rep = 0; rep < 2; rep++) {
        int ri = w + rep * 8;
        int n  = n0 + ri;

        int s = __ldg(&g_offd[n]), e = __ldg(&g_offd[n + 1]);
        float x = 0.f;
        for (int p = s; p < e; p++) {
            int sp = __ldg(&g_spos[p]);
            x += __half2float(g_msgh[(size_t)sp * NC + lane]);
        }
        x *= g_deg[n];

        float h = out[(size_t)n * OUTC + (size_t)(t - 1) * NC + lane];

        float ir = bi[lane], iz = bi[32 + lane], in_ = bi[64 + lane];
        float hr = bh[lane], hz = bh[32 + lane], hn  = bh[64 + lane];
#pragma unroll
        for (int i = 0; i < NC; i++) {
            float xi = __shfl_sync(0xffffffffu, x, i);
            float hi = __shfl_sync(0xffffffffu, h, i);
            ir  = fmaf(xi, Wi[i * 96 + lane],      ir);
            iz  = fmaf(xi, Wi[i * 96 + 32 + lane], iz);
            in_ = fmaf(xi, Wi[i * 96 + 64 + lane], in_);
            hr  = fmaf(hi, Wh[i * 96 + lane],      hr);
            hz  = fmaf(hi, Wh[i * 96 + 32 + lane], hz);
            hn  = fmaf(hi, Wh[i * 96 + 64 + lane], hn);
        }
        float r  = 1.0f / (1.0f + expf(-(ir + hr)));
        float z  = 1.0f / (1.0f + expf(-(iz + hz)));
        float nn = tanhf(in_ + r * hn);
        float hv = (1.0f - z) * nn + z * h;
        out[(size_t)n * OUTC + (size_t)t * NC + lane] = hv;
        As[ri * 40 + lane] = __float2half_rn(hv);
    }
    __syncthreads();

    if (last) return;

    // Phase 2: Q tile for the 16 nodes. Warp w covers cols [w*256, w*256+256).
    wmma::fragment<wmma::matrix_a, 16, 16, 16, __half, wmma::row_major> af[2];
    wmma::load_matrix_sync(af[0], As,      40);
    wmma::load_matrix_sync(af[1], As + 16, 40);
#pragma unroll
    for (int nt = 0; nt < 16; nt++) {
        int col0 = w * 256 + nt * 16;
        wmma::fragment<wmma::accumulator, 16, 16, 16, float> acc;
        wmma::fill_fragment(acc, 0.0f);
#pragma unroll
        for (int ks = 0; ks < 2; ks++) {
            wmma::fragment<wmma::matrix_b, 16, 16, 16, __half, wmma::row_major> bf;
            wmma::load_matrix_sync(bf, g_fW2pp + (size_t)(ks * 16) * 2048 + col0, 2048);
            wmma::mma_sync(acc, af[ks], bf, acc);
        }
        wmma::fragment<wmma::accumulator, 16, 16, 16, __half> hc;
#pragma unroll
        for (int i = 0; i < hc.num_elements; i++)
            hc.x[i] = __float2half_rn(acc.x[i]);
        wmma::store_matrix_sync(g_Q + (size_t)n0 * 2048 + col0, hc, 2048, wmma::mem_row_major);
    }
}

// tail — re-zero CSR counters so every graph replay starts clean
__global__ void cleanup_kernel(int N) {
    int i = blockIdx.x * blockDim.x + threadIdx.x;
    if (i < N) { g_cnt[i] = 0; g_cntd[i] = 0; g_cur[i] = 0; g_curd[i] = 0; }
}

// ---------------------------------------------------------------------------
extern "C" void kernel_launch(void* const* d_in, const int* in_sizes, int n_in,
                              void* d_out, int out_size) {
    const float* hx  = (const float*)d_in[0];
    const int*   ei  = (const int*)d_in[1];
    const float* ef  = (const float*)d_in[2];
    const float* fW1 = (const float*)d_in[3];
    const float* fb1 = (const float*)d_in[4];
    const float* fW2 = (const float*)d_in[5];
    const float* fb2 = (const float*)d_in[6];
    const float* Wi  = (const float*)d_in[7];
    const float* Wh  = (const float*)d_in[8];
    const float* bi  = (const float*)d_in[9];
    const float* bh  = (const float*)d_in[10];
    float* out = (float*)d_out;

    const int N = in_sizes[0] / NC;   // 20000
    const int E = in_sizes[1] / 2;    // 200000
    const int* src = ei;
    const int* dst = ei + E;

    dim3 qgrid((MPAD + 64 * MT_PER_BLK - 1) / (64 * MT_PER_BLK), 2048 / 128);

    prep0_kernel<<<(E * 32 + 255) / 256, 256>>>(ef, fW1, fb1, fW2, hx, src, dst, out, N, E); // 1
    qgemm_kernel<<<qgrid, 256>>>(N);                                                         // 2 (+scan)
    scatter_kernel<<<(E * 32 + 255) / 256, 256>>>(src, dst, N, E);                           // 3

    for (int t = 1; t <= NREP; t++) {
        msg_kernel<<<(N * 32 + 255) / 256, 256>>>(out, fb2, N, t);    // t=1: launch #4
        gruq_kernel<<<N / 16, 256>>>(out, Wi, Wh, bi, bh, N, t, t == NREP);
    }
    cleanup_kernel<<<(N + 255) / 256, 256>>>(N);
}

// round 15
// speedup vs baseline: 1.5387x; 1.5387x over previous
#include <cuda_runtime.h>
#include <cuda_fp16.h>
#include <mma.h>
#include <math.h>

using namespace nvcuda;

#define NNODES 20000
#define NEDGES 200000
#define NC     32
#define FDIM   13
#define FHID   64
#define NREP   10
#define OUTC   (NC * (NREP + 1))   // 352
#define MPAD   20032               // NNODES padded to 64

// Scratch (__device__ globals; allocation-free rule). Zero-initialized at load.
__device__ __half g_Q[(size_t)MPAD * 2048];            // 82 MB, layout [n][k*32+o]
__device__ __half g_h1[(size_t)NEDGES * FHID];         // 25.6 MB (edge order)
__device__ __half g_h1s[(size_t)(NEDGES + 16) * FHID]; // src-sorted (+16 pad rows)
__device__ __half g_fW2pp[32 * 2048];                  // permuted fW2: [i][k*32+o]
__device__ __half g_hxh[(size_t)MPAD * NC];            // fp16 copy of current hx
__device__ __half g_msgh[(size_t)NEDGES * NC];         // msgs fp16, SRC-sorted
__device__ float  g_deg[NNODES];
__device__ int    g_cnt[NNODES], g_cur[NNODES];        // src CSR build
__device__ int    g_cntd[NNODES], g_curd[NNODES];      // dst CSR build
__device__ int    g_off[NNODES + 1];                   // src CSR offsets
__device__ int    g_offd[NNODES + 1];                  // dst CSR offsets
__device__ int    g_spos[NEDGES];                      // dst-sorted pos -> src-sorted pos

// ---------------------------------------------------------------------------
// launch 1 — prep0: h1 (warp/edge) + degree counts + copy0 + fW2 permute
// ---------------------------------------------------------------------------
__global__ void prep0_kernel(const float* __restrict__ ef,
                             const float* __restrict__ fW1,
                             const float* __restrict__ fb1,
                             const float* __restrict__ fW2,
                             const float* __restrict__ hx,
                             const int* __restrict__ src,
                             const int* __restrict__ dst,
                             float* __restrict__ out,
                             int N, int E) {
    int gtid = blockIdx.x * blockDim.x + threadIdx.x;
    int e    = gtid >> 5;
    int lane = gtid & 31;

    if (e < E) {
        float efv = (lane < FDIM) ? ef[(size_t)e * FDIM + lane] : 0.f;
        float a0 = fb1[lane], a1 = fb1[lane + 32];
#pragma unroll
        for (int j = 0; j < FDIM; j++) {
            float x = __shfl_sync(0xffffffffu, efv, j);
            a0 = fmaf(x, fW1[j * FHID + lane],      a0);
            a1 = fmaf(x, fW1[j * FHID + lane + 32], a1);
        }
        g_h1[(size_t)e * FHID + lane]      = __float2half_rn(fmaxf(a0, 0.f));
        g_h1[(size_t)e * FHID + lane + 32] = __float2half_rn(fmaxf(a1, 0.f));
    }
    if (gtid < E) {
        atomicAdd(&g_cnt[src[gtid]], 1);
        atomicAdd(&g_cntd[dst[gtid]], 1);
    }
    if (gtid < N * NC) {
        float v = hx[gtid];
        out[(size_t)(gtid >> 5) * OUTC + (gtid & 31)] = v;
        g_hxh[gtid] = __float2half_rn(v);
    }
    if (gtid < (MPAD - NNODES) * NC)
        g_hxh[(size_t)NNODES * NC + gtid] = __float2half_rn(0.f);
    // fW2 permute: g_fW2pp[i*2048 + k*32 + o] = fW2[k*1024 + i*32 + o]
    if (gtid < 32 * 2048) {
        int i = gtid >> 11, rem = gtid & 2047, k = rem >> 5, o = rem & 31;
        g_fW2pp[gtid] = __float2half_rn(fW2[k * 1024 + i * 32 + o]);
    }
}

// launch 2 — exclusive scans (single block)
__global__ void scan_kernel(int N) {
    __shared__ int part[256];
    int t = threadIdx.x;
    int chunk = (N + 255) / 256;
    int lo = t * chunk, hi = min(lo + chunk, N);

    int s = 0;
    for (int i = lo; i < hi; i++) s += g_cnt[i];
    part[t] = s;
    __syncthreads();
    if (t == 0) {
        int run = 0;
        for (int i = 0; i < 256; i++) { int v = part[i]; part[i] = run; run += v; }
        g_off[N] = run;
    }
    __syncthreads();
    int run = part[t];
    for (int i = lo; i < hi; i++) { g_off[i] = run; run += g_cnt[i]; }
    __syncthreads();

    s = 0;
    for (int i = lo; i < hi; i++) s += g_cntd[i];
    part[t] = s;
    __syncthreads();
    if (t == 0) {
        int run2 = 0;
        for (int i = 0; i < 256; i++) { int v = part[i]; part[i] = run2; run2 += v; }
        g_offd[N] = run2;
    }
    __syncthreads();
    run = part[t];
    for (int i = lo; i < hi; i++) { g_offd[i] = run; run += g_cntd[i]; }
}

// launch 3 — scatter: warp per edge. h1 -> src-sorted g_h1s; spos inverse map.
__global__ void scatter_kernel(const int* __restrict__ src,
                               const int* __restrict__ dst, int N, int E) {
    int gtid = blockIdx.x * blockDim.x + threadIdx.x;
    int e    = gtid >> 5;
    int lane = gtid & 31;
    if (e < E) {
        int ps = 0;
        if (lane == 0) {
            int s = src[e], d = dst[e];
            ps = g_off[s]  + atomicAdd(&g_cur[s], 1);
            int pd = g_offd[d] + atomicAdd(&g_curd[d], 1);
            g_spos[pd] = ps;
        }
        ps = __shfl_sync(0xffffffffu, ps, 0);
        ((int*)g_h1s)[(size_t)ps * 32 + lane] = ((const int*)g_h1)[(size_t)e * 32 + lane];
    }
    if (gtid < N) g_deg[gtid] = 1.0f / fmaxf((float)g_cntd[gtid], 1.0f);
}

// ---------------------------------------------------------------------------
// launch 4 (PROFILED) — qgemm: Q = hxh @ fW2pp.
// Block: 8 M-tiles of 64 x one 128-wide N tile. Bs in smem; B fragments
// reloaded per M-tile (LDSM) instead of register-cached -> lower regs, higher occ.
// ---------------------------------------------------------------------------
#define QBS_LD 136
#define MT_PER_BLK 8

__global__ void qgemm_kernel() {
    __shared__ __align__(16) __half Bs[32 * QBS_LD];

    const int tid = threadIdx.x;
    const int wid = tid >> 5;
    const int wm = wid & 3, wn = wid >> 2;
    const int n0 = blockIdx.y * 128;

#pragma unroll
    for (int i = tid; i < 512; i += 256) {
        int r = i >> 4, s = i & 15;
        *(int4*)(Bs + r * QBS_LD + s * 8) =
            *(const int4*)(g_fW2pp + (size_t)r * 2048 + n0 + s * 8);
    }
    __syncthreads();

    for (int mi = 0; mi < MT_PER_BLK; mi++) {
        int m0 = (blockIdx.x * MT_PER_BLK + mi) * 64;
        if (m0 >= MPAD) break;

        wmma::fragment<wmma::accumulator, 16, 16, 16, float> acc[4];
#pragma unroll
        for (int j = 0; j < 4; j++) wmma::fill_fragment(acc[j], 0.0f);
#pragma unroll
        for (int k = 0; k < 2; k++) {
            wmma::fragment<wmma::matrix_a, 16, 16, 16, __half, wmma::row_major> af;
            wmma::load_matrix_sync(af, g_hxh + (size_t)(m0 + wm * 16) * NC + k * 16, NC);
#pragma unroll
            for (int j = 0; j < 4; j++) {
                wmma::fragment<wmma::matrix_b, 16, 16, 16, __half, wmma::row_major> bf;
                wmma::load_matrix_sync(bf, Bs + (k * 16) * QBS_LD + wn * 64 + j * 16, QBS_LD);
                wmma::mma_sync(acc[j], af, bf, acc[j]);
            }
        }
#pragma unroll
        for (int j = 0; j < 4; j++) {
            wmma::fragment<wmma::accumulator, 16, 16, 16, __half> hc;
#pragma unroll
            for (int i = 0; i < hc.num_elements; i++)
                hc.x[i] = __float2half_rn(acc[j].x[i]);
            wmma::store_matrix_sync(g_Q + (size_t)(m0 + wm * 16) * 2048 + n0 + wn * 64 + j * 16,
                                    hc, 2048, wmma::mem_row_major);
        }
    }
}

// ---------------------------------------------------------------------------
// msg: warp per node, tensor cores, smem-staged Q row. B fragments loaded
// inside the mt loop (no register caching — no reuse for d<=16 anyway).
// MSG[d x 32] = H1s[d x 64] @ Q[n] (64 x 32 k-major), fp32 accum, fp16 out.
// ---------------------------------------------------------------------------
#define QW_LD 40
__global__ void msg_kernel(const float* __restrict__ out,
                           const float* __restrict__ fb2,
                           int N, int t) {
    __shared__ __align__(16) __half Qw[8][64 * QW_LD];   // 5,120 B per warp
    int n    = (blockIdx.x * blockDim.x + threadIdx.x) >> 5;
    int lane = threadIdx.x & 31;
    int w    = (threadIdx.x >> 5) & 7;
    if (n >= N) return;
    int start = __ldg(&g_off[n]);
    int d = __ldg(&g_off[n + 1]) - start;
    if (d == 0) return;

    // stage Q row (4KB): lane copies rows lane and lane+32 (64B each, coalesced)
    {
        const int4* qsrc = (const int4*)(g_Q + (size_t)n * 2048);
#pragma unroll
        for (int rr = 0; rr < 2; rr++) {
            int r = lane + rr * 32;
            int4* dstp = (int4*)(&Qw[w][r * QW_LD]);
#pragma unroll
            for (int j = 0; j < 4; j++)
                dstp[j] = __ldg(qsrc + r * 4 + j);
        }
    }

    // bias: bn[o] = sum_i hx[n,i] * fb2[i*32+o]
    float hxl = out[(size_t)n * OUTC + (size_t)(t - 1) * NC + lane];
    float bn = 0.f;
#pragma unroll
    for (int i = 0; i < NC; i++)
        bn = fmaf(__shfl_sync(0xffffffffu, hxl, i), fb2[i * 32 + lane], bn);
    __syncwarp();

    for (int mt = 0; mt < d; mt += 16) {
        wmma::fragment<wmma::accumulator, 16, 16, 16, float> acc0, acc1;
        wmma::fill_fragment(acc0, 0.0f);
        wmma::fill_fragment(acc1, 0.0f);
#pragma unroll
        for (int kk = 0; kk < 4; kk++) {
            wmma::fragment<wmma::matrix_a, 16, 16, 16, __half, wmma::row_major> af;
            wmma::load_matrix_sync(af, g_h1s + (size_t)(start + mt) * FHID + kk * 16, FHID);
            wmma::fragment<wmma::matrix_b, 16, 16, 16, __half, wmma::row_major> bf;
            wmma::load_matrix_sync(bf, &Qw[w][(kk * 16) * QW_LD], QW_LD);
            wmma::mma_sync(acc0, af, bf, acc0);
            wmma::load_matrix_sync(bf, &Qw[w][(kk * 16) * QW_LD + 16], QW_LD);
            wmma::mma_sync(acc1, af, bf, acc1);
        }
        // store C into the tail of the warp's staging area (doesn't clobber
        // Q rows still needed if d > 16: use rows 0.. only after last use).
        float* Cst = (float*)(&Qw[w][0]);
        if (mt + 16 >= d) {             // last tile: Q no longer needed
            wmma::store_matrix_sync(Cst,      acc0, 32, wmma::mem_row_major);
            wmma::store_matrix_sync(Cst + 16, acc1, 32, wmma::mem_row_major);
            __syncwarp();
            int rows = d - mt;
            for (int r = 0; r < rows; r++)
                g_msgh[(size_t)(start + mt + r) * NC + lane] =
                    __float2half_rn(Cst[r * 32 + lane] + bn);
            __syncwarp();
        } else {                        // rare (d > 16): spill via registers
            __syncwarp();
            // write acc via smem in two halves, reusing only rows we re-stage
            // safe path: store to staging tail (rows 48..63 = 16*40 halves = 1280B < 2048B of C)
            float* Ct = (float*)(&Qw[w][48 * QW_LD]);  // 16*40*2B = 1280B区域不足
            // fall back: store then immediately restage Q rows below
            wmma::store_matrix_sync(Cst,      acc0, 32, wmma::mem_row_major);
            wmma::store_matrix_sync(Cst + 16, acc1, 32, wmma::mem_row_major);
            __syncwarp();
            (void)Ct;
            for (int r = 0; r < 16; r++)
                g_msgh[(size_t)(start + mt + r) * NC + lane] =
                    __float2half_rn(Cst[r * 32 + lane] + bn);
            __syncwarp();
            // re-stage clobbered Q rows (rows 0..31 cover 2048B of C exactly)
            const int4* qsrc = (const int4*)(g_Q + (size_t)n * 2048);
            int r = lane;                       // rows 0..31
            int4* dstp = (int4*)(&Qw[w][r * QW_LD]);
#pragma unroll
            for (int j = 0; j < 4; j++)
                dstp[j] = __ldg(qsrc + r * 4 + j);
            __syncwarp();
        }
    }
}

// ---------------------------------------------------------------------------
// GRU: warp per node. Gather fp16 msgs via dst-CSR + spos, then GRU math.
// ---------------------------------------------------------------------------
__global__ void gru_kernel(float* __restrict__ out,
                           const float* __restrict__ Wi,
                           const float* __restrict__ Wh,
                           const float* __restrict__ bi,
                           const float* __restrict__ bh,
                           int N, int t) {
    int n    = (blockIdx.x * blockDim.x + threadIdx.x) >> 5;
    int lane = threadIdx.x & 31;
    if (n >= N) return;

    int s = __ldg(&g_offd[n]), e = __ldg(&g_offd[n + 1]);
    float x = 0.f;
    for (int p = s; p < e; p++) {
        int sp = __ldg(&g_spos[p]);
        x += __half2float(g_msgh[(size_t)sp * NC + lane]);
    }
    x *= g_deg[n];

    float h = out[(size_t)n * OUTC + (size_t)(t - 1) * NC + lane];

    float ir = bi[lane], iz = bi[32 + lane], in_ = bi[64 + lane];
    float hr = bh[lane], hz = bh[32 + lane], hn  = bh[64 + lane];
#pragma unroll
    for (int i = 0; i < NC; i++) {
        float xi = __shfl_sync(0xffffffffu, x, i);
        float hi = __shfl_sync(0xffffffffu, h, i);
        ir  = fmaf(xi, Wi[i * 96 + lane],      ir);
        iz  = fmaf(xi, Wi[i * 96 + 32 + lane], iz);
        in_ = fmaf(xi, Wi[i * 96 + 64 + lane], in_);
        hr  = fmaf(hi, Wh[i * 96 + lane],      hr);
        hz  = fmaf(hi, Wh[i * 96 + 32 + lane], hz);
        hn  = fmaf(hi, Wh[i * 96 + 64 + lane], hn);
    }
    float r  = 1.0f / (1.0f + expf(-(ir + hr)));
    float z  = 1.0f / (1.0f + expf(-(iz + hz)));
    float nn = tanhf(in_ + r * hn);
    float hv = (1.0f - z) * nn + z * h;
    out[(size_t)n * OUTC + (size_t)t * NC + lane] = hv;
    g_hxh[(size_t)n * NC + lane] = __float2half_rn(hv);
}

// tail — re-zero CSR counters so every graph replay starts clean
__global__ void cleanup_kernel(int N) {
    int i = blockIdx.x * blockDim.x + threadIdx.x;
    if (i < N) { g_cnt[i] = 0; g_cntd[i] = 0; g_cur[i] = 0; g_curd[i] = 0; }
}

// ---------------------------------------------------------------------------
extern "C" void kernel_launch(void* const* d_in, const int* in_sizes, int n_in,
                              void* d_out, int out_size) {
    const float* hx  = (const float*)d_in[0];
    const int*   ei  = (const int*)d_in[1];
    const float* ef  = (const float*)d_in[2];
    const float* fW1 = (const float*)d_in[3];
    const float* fb1 = (const float*)d_in[4];
    const float* fW2 = (const float*)d_in[5];
    const float* fb2 = (const float*)d_in[6];
    const float* Wi  = (const float*)d_in[7];
    const float* Wh  = (const float*)d_in[8];
    const float* bi  = (const float*)d_in[9];
    const float* bh  = (const float*)d_in[10];
    float* out = (float*)d_out;

    const int N = in_sizes[0] / NC;   // 20000
    const int E = in_sizes[1] / 2;    // 200000
    const int* src = ei;
    const int* dst = ei + E;

    dim3 qgrid((MPAD + 64 * MT_PER_BLK - 1) / (64 * MT_PER_BLK), 2048 / 128);

    prep0_kernel<<<(E * 32 + 255) / 256, 256>>>(ef, fW1, fb1, fW2, hx, src, dst, out, N, E);
    scan_kernel<<<1, 256>>>(N);
    scatter_kernel<<<(E * 32 + 255) / 256, 256>>>(src, dst, N, E);

    for (int t = 1; t <= NREP; t++) {
        qgemm_kernel<<<qgrid, 256>>>();                                   // t=1: launch #4
        msg_kernel<<<(N * 32 + 255) / 256, 256>>>(out, fb2, N, t);
        gru_kernel<<<(N * 32 + 255) / 256, 256>>>(out, Wi, Wh, bi, bh, N, t);
    }
    cleanup_kernel<<<(N + 255) / 256, 256>>>(N);
}

// round 16
// speedup vs baseline: 1.6216x; 1.0539x over previous
#include <cuda_runtime.h>
#include <cuda_fp16.h>
#include <mma.h>
#include <math.h>

using namespace nvcuda;

#define NNODES 20000
#define NEDGES 200000
#define NC     32
#define FDIM   13
#define FHID   64
#define NREP   10
#define OUTC   (NC * (NREP + 1))   // 352
#define MPAD   20032               // NNODES padded to 64

// Scratch (__device__ globals; allocation-free rule). Zero-initialized at load.
__device__ __half g_Q[(size_t)MPAD * 2048];            // 82 MB, layout [n][k*32+o]
__device__ __half g_h1[(size_t)NEDGES * FHID];         // 25.6 MB (edge order)
__device__ __half g_h1s[(size_t)(NEDGES + 16) * FHID]; // src-sorted (+16 pad rows)
__device__ __half g_fW2pp[32 * 2048];                  // permuted fW2: [i][k*32+o]
__device__ __half g_hxh[(size_t)MPAD * NC];            // fp16 copy of current hx
__device__ __half g_msgh[(size_t)NEDGES * NC];         // msgs fp16, DST-sorted
__device__ float  g_deg[NNODES];
__device__ int    g_cnt[NNODES], g_cur[NNODES];        // src CSR build
__device__ int    g_cntd[NNODES], g_curd[NNODES];      // dst CSR build
__device__ int    g_off[NNODES + 1];                   // src CSR offsets
__device__ int    g_offd[NNODES + 1];                  // dst CSR offsets
__device__ int    g_dpos[NEDGES];                      // src-sorted pos -> dst-sorted pos

// ---------------------------------------------------------------------------
// launch 1 — prep0: h1 (warp/edge) + degree counts + copy0 + fW2 permute
// ---------------------------------------------------------------------------
__global__ void prep0_kernel(const float* __restrict__ ef,
                             const float* __restrict__ fW1,
                             const float* __restrict__ fb1,
                             const float* __restrict__ fW2,
                             const float* __restrict__ hx,
                             const int* __restrict__ src,
                             const int* __restrict__ dst,
                             float* __restrict__ out,
                             int N, int E) {
    int gtid = blockIdx.x * blockDim.x + threadIdx.x;
    int e    = gtid >> 5;
    int lane = gtid & 31;

    if (e < E) {
        float efv = (lane < FDIM) ? ef[(size_t)e * FDIM + lane] : 0.f;
        float a0 = fb1[lane], a1 = fb1[lane + 32];
#pragma unroll
        for (int j = 0; j < FDIM; j++) {
            float x = __shfl_sync(0xffffffffu, efv, j);
            a0 = fmaf(x, fW1[j * FHID + lane],      a0);
            a1 = fmaf(x, fW1[j * FHID + lane + 32], a1);
        }
        g_h1[(size_t)e * FHID + lane]      = __float2half_rn(fmaxf(a0, 0.f));
        g_h1[(size_t)e * FHID + lane + 32] = __float2half_rn(fmaxf(a1, 0.f));
    }
    if (gtid < E) {
        atomicAdd(&g_cnt[src[gtid]], 1);
        atomicAdd(&g_cntd[dst[gtid]], 1);
    }
    if (gtid < N * NC) {
        float v = hx[gtid];
        out[(size_t)(gtid >> 5) * OUTC + (gtid & 31)] = v;
        g_hxh[gtid] = __float2half_rn(v);
    }
    if (gtid < (MPAD - NNODES) * NC)
        g_hxh[(size_t)NNODES * NC + gtid] = __float2half_rn(0.f);
    // fW2 permute: g_fW2pp[i*2048 + k*32 + o] = fW2[k*1024 + i*32 + o]
    if (gtid < 32 * 2048) {
        int i = gtid >> 11, rem = gtid & 2047, k = rem >> 5, o = rem & 31;
        g_fW2pp[gtid] = __float2half_rn(fW2[k * 1024 + i * 32 + o]);
    }
}

// ---------------------------------------------------------------------------
// launch 2 — qgemm (+ CSR scans on first call by block(0,0)):
// Q = hxh @ fW2pp. 8 M-tiles x 128-wide N tile. A pipelined via smem,
// B fragments register-cached (R13 best-measured config).
// ---------------------------------------------------------------------------
#define QBS_LD 136
#define MT_PER_BLK 8

__global__ void qgemm_kernel(int N, int do_scan) {
    __shared__ __align__(16) __half Bs[32 * QBS_LD];
    __shared__ __align__(16) __half As[64 * 40];
    __shared__ int part[256];

    const int tid = threadIdx.x;
    const int wid = tid >> 5;
    const int wm = wid & 3, wn = wid >> 2;
    const int n0 = blockIdx.y * 128;

    if (do_scan && blockIdx.x == 0 && blockIdx.y == 0) {
        int chunk = (N + 255) / 256;
        int lo = tid * chunk, hi = min(lo + chunk, N);
        int s = 0;
        for (int i = lo; i < hi; i++) s += g_cnt[i];
        part[tid] = s;
        __syncthreads();
        if (tid == 0) {
            int run = 0;
            for (int i = 0; i < 256; i++) { int v = part[i]; part[i] = run; run += v; }
            g_off[N] = run;
        }
        __syncthreads();
        int run = part[tid];
        for (int i = lo; i < hi; i++) { g_off[i] = run; run += g_cnt[i]; }
        __syncthreads();

        s = 0;
        for (int i = lo; i < hi; i++) s += g_cntd[i];
        part[tid] = s;
        __syncthreads();
        if (tid == 0) {
            int run2 = 0;
            for (int i = 0; i < 256; i++) { int v = part[i]; part[i] = run2; run2 += v; }
            g_offd[N] = run2;
        }
        __syncthreads();
        run = part[tid];
        for (int i = lo; i < hi; i++) { g_offd[i] = run; run += g_cntd[i]; }
        __syncthreads();
    }

#pragma unroll
    for (int i = tid; i < 512; i += 256) {
        int r = i >> 4, s = i & 15;
        *(int4*)(Bs + r * QBS_LD + s * 8) =
            *(const int4*)(g_fW2pp + (size_t)r * 2048 + n0 + s * 8);
    }
    __syncthreads();

    wmma::fragment<wmma::matrix_b, 16, 16, 16, __half, wmma::row_major> bf[2][4];
#pragma unroll
    for (int k = 0; k < 2; k++)
#pragma unroll
        for (int j = 0; j < 4; j++)
            wmma::load_matrix_sync(bf[k][j], Bs + (k * 16) * QBS_LD + wn * 64 + j * 16, QBS_LD);

    // A pipeline: 1 int4 per thread per tile (64 rows x 4 int4)
    const int ar = tid >> 2, as = tid & 3;
    int4 a_pref;
    {
        int row = min(blockIdx.x * MT_PER_BLK * 64 + ar, MPAD - 1);
        a_pref = *(const int4*)(g_hxh + (size_t)row * NC + as * 8);
    }

    for (int mi = 0; mi < MT_PER_BLK; mi++) {
        int m0 = (blockIdx.x * MT_PER_BLK + mi) * 64;
        if (m0 >= MPAD) break;

        *(int4*)(As + ar * 40 + as * 8) = a_pref;
        __syncthreads();

        if (mi + 1 < MT_PER_BLK) {   // prefetch next tile (overlaps mma below)
            int row = min((blockIdx.x * MT_PER_BLK + mi + 1) * 64 + ar, MPAD - 1);
            a_pref = *(const int4*)(g_hxh + (size_t)row * NC + as * 8);
        }

        wmma::fragment<wmma::accumulator, 16, 16, 16, float> acc[4];
#pragma unroll
        for (int j = 0; j < 4; j++) wmma::fill_fragment(acc[j], 0.0f);
#pragma unroll
        for (int k = 0; k < 2; k++) {
            wmma::fragment<wmma::matrix_a, 16, 16, 16, __half, wmma::row_major> af;
            wmma::load_matrix_sync(af, As + (wm * 16) * 40 + k * 16, 40);
#pragma unroll
            for (int j = 0; j < 4; j++)
                wmma::mma_sync(acc[j], af, bf[k][j], acc[j]);
        }
#pragma unroll
        for (int j = 0; j < 4; j++) {
            wmma::fragment<wmma::accumulator, 16, 16, 16, __half> hc;
#pragma unroll
            for (int i = 0; i < hc.num_elements; i++)
                hc.x[i] = __float2half_rn(acc[j].x[i]);
            wmma::store_matrix_sync(g_Q + (size_t)(m0 + wm * 16) * 2048 + n0 + wn * 64 + j * 16,
                                    hc, 2048, wmma::mem_row_major);
        }
        __syncthreads();   // all warps done reading As before next overwrite
    }
}

// launch 3 — scatter: warp per edge. h1 -> src-sorted g_h1s; dpos map; invdeg.
__global__ void scatter_kernel(const int* __restrict__ src,
                               const int* __restrict__ dst, int N, int E) {
    int gtid = blockIdx.x * blockDim.x + threadIdx.x;
    int e    = gtid >> 5;
    int lane = gtid & 31;
    if (e < E) {
        int ps = 0;
        if (lane == 0) {
            int s = src[e], d = dst[e];
            ps = g_off[s]  + atomicAdd(&g_cur[s], 1);
            int pd = g_offd[d] + atomicAdd(&g_curd[d], 1);
            g_dpos[ps] = pd;
        }
        ps = __shfl_sync(0xffffffffu, ps, 0);
        ((int*)g_h1s)[(size_t)ps * 32 + lane] = ((const int*)g_h1)[(size_t)e * 32 + lane];
    }
    if (gtid < N) g_deg[gtid] = 1.0f / fmaxf((float)g_cntd[gtid], 1.0f);
}

// ---------------------------------------------------------------------------
// launch 4 (PROFILED) — msg: warp per node, REVERSED node order (reads the
// most-recently-written Q rows first -> L2 hits). Q row staged via smem.
// MSG[d x 32] = H1s[d x 64] @ Q[n]; fp32 accum; fp16 out scattered to
// dst-sorted positions via dpos (gru then reads contiguously).
// ---------------------------------------------------------------------------
#define QW_LD 40
__global__ void msg_kernel(const float* __restrict__ out,
                           const float* __restrict__ fb2,
                           int N, int t) {
    __shared__ __align__(16) __half Qw[8][64 * QW_LD];   // 5,120 B per warp
    int gw   = (blockIdx.x * blockDim.x + threadIdx.x) >> 5;
    int lane = threadIdx.x & 31;
    int w    = (threadIdx.x >> 5) & 7;
    if (gw >= N) return;
    int n = N - 1 - gw;                                   // reversed order
    int start = __ldg(&g_off[n]);
    int d = __ldg(&g_off[n + 1]) - start;
    if (d == 0) return;

    // stage Q row (4KB): lane copies rows lane and lane+32 (64B each, coalesced)
    {
        const int4* qsrc = (const int4*)(g_Q + (size_t)n * 2048);
#pragma unroll
        for (int rr = 0; rr < 2; rr++) {
            int r = lane + rr * 32;
            int4* dstp = (int4*)(&Qw[w][r * QW_LD]);
#pragma unroll
            for (int j = 0; j < 4; j++)
                dstp[j] = __ldg(qsrc + r * 4 + j);
        }
    }

    // bias: bn[o] = sum_i hx[n,i] * fb2[i*32+o]
    float hxl = out[(size_t)n * OUTC + (size_t)(t - 1) * NC + lane];
    float bn = 0.f;
#pragma unroll
    for (int i = 0; i < NC; i++)
        bn = fmaf(__shfl_sync(0xffffffffu, hxl, i), fb2[i * 32 + lane], bn);
    __syncwarp();

    wmma::fragment<wmma::matrix_b, 16, 16, 16, __half, wmma::row_major> bf[4][2];
#pragma unroll
    for (int kk = 0; kk < 4; kk++)
#pragma unroll
        for (int j = 0; j < 2; j++)
            wmma::load_matrix_sync(bf[kk][j], &Qw[w][(kk * 16) * QW_LD + j * 16], QW_LD);
    __syncwarp();

    float* Cst = (float*)(&Qw[w][0]);   // alias warp staging (B-frags in regs)
    for (int mt = 0; mt < d; mt += 16) {
        wmma::fragment<wmma::accumulator, 16, 16, 16, float> acc0, acc1;
        wmma::fill_fragment(acc0, 0.0f);
        wmma::fill_fragment(acc1, 0.0f);
#pragma unroll
        for (int kk = 0; kk < 4; kk++) {
            wmma::fragment<wmma::matrix_a, 16, 16, 16, __half, wmma::row_major> af;
            wmma::load_matrix_sync(af, g_h1s + (size_t)(start + mt) * FHID + kk * 16, FHID);
            wmma::mma_sync(acc0, af, bf[kk][0], acc0);
            wmma::mma_sync(acc1, af, bf[kk][1], acc1);
        }
        int rows = min(16, d - mt);
        int dpv = (lane < rows) ? __ldg(&g_dpos[start + mt + lane]) : 0;
        wmma::store_matrix_sync(Cst,      acc0, 32, wmma::mem_row_major);
        wmma::store_matrix_sync(Cst + 16, acc1, 32, wmma::mem_row_major);
        __syncwarp();
        for (int r = 0; r < rows; r++) {
            int dr = __shfl_sync(0xffffffffu, dpv, r);
            g_msgh[(size_t)dr * NC + lane] =
                __float2half_rn(Cst[r * 32 + lane] + bn);
        }
        __syncwarp();
    }
}

// ---------------------------------------------------------------------------
// GRU: warp per node. CONTIGUOUS fp16 msg reads over dst-CSR, then GRU math.
// ---------------------------------------------------------------------------
__global__ void gru_kernel(float* __restrict__ out,
                           const float* __restrict__ Wi,
                           const float* __restrict__ Wh,
                           const float* __restrict__ bi,
                           const float* __restrict__ bh,
                           int N, int t) {
    int n    = (blockIdx.x * blockDim.x + threadIdx.x) >> 5;
    int lane = threadIdx.x & 31;
    if (n >= N) return;

    int s = __ldg(&g_offd[n]), e = __ldg(&g_offd[n + 1]);
    float x = 0.f;
    for (int p = s; p < e; p++)
        x += __half2float(g_msgh[(size_t)p * NC + lane]);
    x *= g_deg[n];

    float h = out[(size_t)n * OUTC + (size_t)(t - 1) * NC + lane];

    float ir = bi[lane], iz = bi[32 + lane], in_ = bi[64 + lane];
    float hr = bh[lane], hz = bh[32 + lane], hn  = bh[64 + lane];
#pragma unroll
    for (int i = 0; i < NC; i++) {
        float xi = __shfl_sync(0xffffffffu, x, i);
        float hi = __shfl_sync(0xffffffffu, h, i);
        ir  = fmaf(xi, Wi[i * 96 + lane],      ir);
        iz  = fmaf(xi, Wi[i * 96 + 32 + lane], iz);
        in_ = fmaf(xi, Wi[i * 96 + 64 + lane], in_);
        hr  = fmaf(hi, Wh[i * 96 + lane],      hr);
        hz  = fmaf(hi, Wh[i * 96 + 32 + lane], hz);
        hn  = fmaf(hi, Wh[i * 96 + 64 + lane], hn);
    }
    float r  = 1.0f / (1.0f + expf(-(ir + hr)));
    float z  = 1.0f / (1.0f + expf(-(iz + hz)));
    float nn = tanhf(in_ + r * hn);
    float hv = (1.0f - z) * nn + z * h;
    out[(size_t)n * OUTC + (size_t)t * NC + lane] = hv;
    g_hxh[(size_t)n * NC + lane] = __float2half_rn(hv);
}

// tail — re-zero CSR counters so every graph replay starts clean
__global__ void cleanup_kernel(int N) {
    int i = blockIdx.x * blockDim.x + threadIdx.x;
    if (i < N) { g_cnt[i] = 0; g_cntd[i] = 0; g_cur[i] = 0; g_curd[i] = 0; }
}

// ---------------------------------------------------------------------------
extern "C" void kernel_launch(void* const* d_in, const int* in_sizes, int n_in,
                              void* d_out, int out_size) {
    const float* hx  = (const float*)d_in[0];
    const int*   ei  = (const int*)d_in[1];
    const float* ef  = (const float*)d_in[2];
    const float* fW1 = (const float*)d_in[3];
    const float* fb1 = (const float*)d_in[4];
    const float* fW2 = (const float*)d_in[5];
    const float* fb2 = (const float*)d_in[6];
    const float* Wi  = (const float*)d_in[7];
    const float* Wh  = (const float*)d_in[8];
    const float* bi  = (const float*)d_in[9];
    const float* bh  = (const float*)d_in[10];
    float* out = (float*)d_out;

    const int N = in_sizes[0] / NC;   // 20000
    const int E = in_sizes[1] / 2;    // 200000
    const int* src = ei;
    const int* dst = ei + E;

    dim3 qgrid((MPAD + 64 * MT_PER_BLK - 1) / (64 * MT_PER_BLK), 2048 / 128);

    prep0_kernel<<<(E * 32 + 255) / 256, 256>>>(ef, fW1, fb1, fW2, hx, src, dst, out, N, E); // 1
    qgemm_kernel<<<qgrid, 256>>>(N, 1);                                                      // 2 (+scan)
    scatter_kernel<<<(E * 32 + 255) / 256, 256>>>(src, dst, N, E);                           // 3

    for (int t = 1; t <= NREP; t++) {
        msg_kernel<<<(N * 32 + 255) / 256, 256>>>(out, fb2, N, t);     // t=1: launch #4 (profiled)
        gru_kernel<<<(N * 32 + 255) / 256, 256>>>(out, Wi, Wh, bi, bh, N, t);
        if (t < NREP) qgemm_kernel<<<qgrid, 256>>>(N, 0);
    }
    cleanup_kernel<<<(N + 255) / 256, 256>>>(N);
}